// round 2
// baseline (speedup 1.0000x reference)
#include <cuda_runtime.h>
#include <math.h>

// Problem constants
#define BATCH 2
#define SEQ   2048
#define DIMK  2048
#define NH    32
#define NKV   8
#define HD    64
#define NREP  4
#define MTOT  (BATCH*SEQ)      // 4096
#define QDIM  (NH*HD)          // 2048
#define KVDIM (NKV*HD)         // 512

// Scratch (global device arrays; no allocation allowed)
__device__ float g_q[MTOT*QDIM];
__device__ float g_k[MTOT*KVDIM];
__device__ float g_v[MTOT*KVDIM];
__device__ float g_o[MTOT*QDIM];
__device__ int   g_docstart[MTOT];

// ---------------------------------------------------------------------------
// SGEMM: C[m,n] = sum_k A[m*K+k] * B[n*K+k]   (C = A @ B^T, both row-major)
// BM=BN=128, BK=8, TM=TN=8, 256 threads.
// ---------------------------------------------------------------------------
__global__ __launch_bounds__(256) void sgemm_tn(
    const float* __restrict__ A, const float* __restrict__ B,
    float* __restrict__ C, int M, int N, int K)
{
    __shared__ float As[8][128];
    __shared__ float Bs[8][128];

    const int tid = threadIdx.x;
    const int m0 = blockIdx.y * 128;
    const int n0 = blockIdx.x * 128;

    const int lr = tid >> 1;        // 0..127
    const int lc = (tid & 1) * 4;   // 0 or 4
    const int tr = tid >> 4;        // 0..15
    const int tc = tid & 15;        // 0..15

    float acc[8][8];
    #pragma unroll
    for (int i = 0; i < 8; i++)
        #pragma unroll
        for (int j = 0; j < 8; j++) acc[i][j] = 0.f;

    const float* Aptr = A + (size_t)(m0 + lr) * K + lc;
    const float* Bptr = B + (size_t)(n0 + lr) * K + lc;

    for (int k0 = 0; k0 < K; k0 += 8) {
        float4 a4 = *reinterpret_cast<const float4*>(Aptr + k0);
        float4 b4 = *reinterpret_cast<const float4*>(Bptr + k0);
        As[lc+0][lr] = a4.x; As[lc+1][lr] = a4.y;
        As[lc+2][lr] = a4.z; As[lc+3][lr] = a4.w;
        Bs[lc+0][lr] = b4.x; Bs[lc+1][lr] = b4.y;
        Bs[lc+2][lr] = b4.z; Bs[lc+3][lr] = b4.w;
        __syncthreads();

        #pragma unroll
        for (int kk = 0; kk < 8; kk++) {
            float rm[8], rn[8];
            #pragma unroll
            for (int i = 0; i < 4; i++) {
                rm[i]   = As[kk][tr*8 + i];
                rm[i+4] = As[kk][tr*8 + 4 + i];
                rn[i]   = Bs[kk][tc*8 + i];
                rn[i+4] = Bs[kk][tc*8 + 4 + i];
            }
            #pragma unroll
            for (int i = 0; i < 8; i++)
                #pragma unroll
                for (int j = 0; j < 8; j++)
                    acc[i][j] = fmaf(rm[i], rn[j], acc[i][j]);
        }
        __syncthreads();
    }

    #pragma unroll
    for (int i = 0; i < 8; i++) {
        float* crow = C + (size_t)(m0 + tr*8 + i) * N + n0 + tc*8;
        #pragma unroll
        for (int j = 0; j < 8; j += 4) {
            float4 v = make_float4(acc[i][j], acc[i][j+1], acc[i][j+2], acc[i][j+3]);
            *reinterpret_cast<float4*>(crow + j) = v;
        }
    }
}

// ---------------------------------------------------------------------------
// RoPE (in place) with optional folded scale. Layout: buf[bs, h*HD + d].
// out[:d/2] = x1*c - x2*s ; out[d/2:] = x2*c + x1*s, c/s indexed by (seq pos, d)
// ---------------------------------------------------------------------------
__global__ void rope_kernel(float* __restrict__ buf,
                            const float* __restrict__ cosb,
                            const float* __restrict__ sinb,
                            int heads, float scale)
{
    int idx = blockIdx.x * blockDim.x + threadIdx.x;
    int total = MTOT * heads * (HD/2);
    if (idx >= total) return;
    int d  = idx % (HD/2);
    int h  = (idx / (HD/2)) % heads;
    int bs = idx / ((HD/2) * heads);
    int s  = bs % SEQ;
    float c  = cosb[s*(HD/2) + d];
    float sn = sinb[s*(HD/2) + d];
    float* base = buf + (size_t)bs * heads * HD + h * HD;
    float x1 = base[d];
    float x2 = base[d + HD/2];
    base[d]        = (x1*c - x2*sn) * scale;
    base[d + HD/2] = (x2*c + x1*sn) * scale;
}

// ---------------------------------------------------------------------------
// doc_start: first index j with doc_ids[b][j] == doc_ids[b][s] (sorted rows)
// ---------------------------------------------------------------------------
__global__ void docstart_kernel(const int* __restrict__ doc_ids)
{
    int idx = blockIdx.x * blockDim.x + threadIdx.x;
    if (idx >= MTOT) return;
    int b = idx / SEQ, s = idx % SEQ;
    const int* row = doc_ids + b * SEQ;
    int v = row[s];
    int lo = 0, hi = s;
    while (lo < hi) {
        int mid = (lo + hi) >> 1;
        if (row[mid] < v) lo = mid + 1; else hi = mid;
    }
    g_docstart[idx] = lo;
}

// ---------------------------------------------------------------------------
// Flash attention, fp32, BQ=64 x BK=64 tiles, 128 threads.
// Valid keys for query qi: kj in [doc_start[qi], qi]  (doc_ids sorted).
// Thread (tr=tid/16, tc=tid%16): owns rows m=tr*8..+7, cols n=tc*4..+3.
// smem: Qs[d][m] stride 65 (once/block), Ks[d][j] stride 64 (per tile),
//       Vs[j][d] stride 64, Ps[j][m] stride 65.
// ---------------------------------------------------------------------------
#define QS_STRIDE 65
#define PS_STRIDE 65
#define FA_SMEM_FLOATS (64*QS_STRIDE + 64*64 + 64*64 + 64*PS_STRIDE)

__global__ __launch_bounds__(128) void flash_kernel(
    const float* __restrict__ qb, const float* __restrict__ kb,
    const float* __restrict__ vb, float* __restrict__ ob)
{
    extern __shared__ float sm[];
    float* Qs = sm;                      // [64][65]
    float* Ks = Qs + 64*QS_STRIDE;       // [64][64]
    float* Vs = Ks + 64*64;              // [64][64]
    float* Ps = Vs + 64*64;              // [64][65]

    const int tid = threadIdx.x;
    const int q0  = blockIdx.x * 64;
    const int h   = blockIdx.y;
    const int b   = blockIdx.z;
    const int hk  = h / NREP;

    const int tr = tid >> 4;   // 0..7
    const int tc = tid & 15;   // 0..15

    // ---- load Q tile transposed into Qs[d][m] (Q already scaled by 1/8) ----
    {
        int m    = tid & 63;
        int half = tid >> 6;   // 0/1
        const float* qrow = qb + (size_t)(b*SEQ + q0 + m) * QDIM + h * HD;
        #pragma unroll
        for (int i = 0; i < 8; i++) {
            int d0 = half*32 + i*4;
            float4 v = *reinterpret_cast<const float4*>(qrow + d0);
            Qs[(d0+0)*QS_STRIDE + m] = v.x;
            Qs[(d0+1)*QS_STRIDE + m] = v.y;
            Qs[(d0+2)*QS_STRIDE + m] = v.z;
            Qs[(d0+3)*QS_STRIDE + m] = v.w;
        }
    }

    // per-row doc starts + running stats
    int   myds[8];
    float m_run[8], l_run[8], oacc[8][4];
    #pragma unroll
    for (int i = 0; i < 8; i++) {
        myds[i]  = g_docstart[b*SEQ + q0 + tr*8 + i];
        m_run[i] = -1e30f;
        l_run[i] = 0.f;
        #pragma unroll
        for (int j = 0; j < 4; j++) oacc[i][j] = 0.f;
    }

    const int kstart = g_docstart[b*SEQ + q0] & ~63;
    __syncthreads();

    for (int k0 = kstart; k0 <= q0; k0 += 64) {
        // ---- load K transposed Ks[d][j]; V natural Vs[j][d] ----
        {
            int j    = tid & 63;
            int half = tid >> 6;
            const float* krow = kb + (size_t)(b*SEQ + k0 + j) * KVDIM + hk * HD;
            #pragma unroll
            for (int i = 0; i < 8; i++) {
                int d0 = half*32 + i*4;
                float4 v = *reinterpret_cast<const float4*>(krow + d0);
                Ks[(d0+0)*64 + j] = v.x;
                Ks[(d0+1)*64 + j] = v.y;
                Ks[(d0+2)*64 + j] = v.z;
                Ks[(d0+3)*64 + j] = v.w;
            }
            int jv = tid >> 4;          // 0..7
            int d0 = (tid & 15) * 4;
            #pragma unroll
            for (int it = 0; it < 8; it++) {
                int jj = jv + it*8;
                const float* vrow = vb + (size_t)(b*SEQ + k0 + jj) * KVDIM + hk * HD;
                float4 v = *reinterpret_cast<const float4*>(vrow + d0);
                *reinterpret_cast<float4*>(&Vs[jj*64 + d0]) = v;
            }
        }
        __syncthreads();

        // ---- GEMM1: s[8][4] = Q K^T ----
        float s[8][4];
        #pragma unroll
        for (int i = 0; i < 8; i++)
            #pragma unroll
            for (int j = 0; j < 4; j++) s[i][j] = 0.f;

        #pragma unroll 4
        for (int kk = 0; kk < 64; kk++) {
            float rm[8];
            #pragma unroll
            for (int i = 0; i < 8; i++) rm[i] = Qs[kk*QS_STRIDE + tr*8 + i];
            float4 rn = *reinterpret_cast<const float4*>(&Ks[kk*64 + tc*4]);
            #pragma unroll
            for (int i = 0; i < 8; i++) {
                s[i][0] = fmaf(rm[i], rn.x, s[i][0]);
                s[i][1] = fmaf(rm[i], rn.y, s[i][1]);
                s[i][2] = fmaf(rm[i], rn.z, s[i][2]);
                s[i][3] = fmaf(rm[i], rn.w, s[i][3]);
            }
        }

        // ---- mask + online softmax (row reductions over 16 tc lanes) ----
        #pragma unroll
        for (int i = 0; i < 8; i++) {
            int qi = q0 + tr*8 + i;
            float mloc = -1e30f;
            #pragma unroll
            for (int j = 0; j < 4; j++) {
                int kj = k0 + tc*4 + j;
                bool ok = (kj <= qi) && (kj >= myds[i]);
                if (!ok) s[i][j] = -1e30f;
                mloc = fmaxf(mloc, s[i][j]);
            }
            #pragma unroll
            for (int off = 8; off > 0; off >>= 1)
                mloc = fmaxf(mloc, __shfl_xor_sync(0xffffffffu, mloc, off));

            float mnew = fmaxf(m_run[i], mloc);
            float corr = __expf(m_run[i] - mnew);
            m_run[i] = mnew;

            float lsum = 0.f;
            #pragma unroll
            for (int j = 0; j < 4; j++) {
                float p = (s[i][j] > -1e29f) ? __expf(s[i][j] - mnew) : 0.f;
                s[i][j] = p;
                lsum += p;
            }
            #pragma unroll
            for (int off = 8; off > 0; off >>= 1)
                lsum += __shfl_xor_sync(0xffffffffu, lsum, off);

            l_run[i] = l_run[i] * corr + lsum;
            #pragma unroll
            for (int d = 0; d < 4; d++) oacc[i][d] *= corr;
        }

        // ---- write P^T to Ps[j][m] ----
        #pragma unroll
        for (int j = 0; j < 4; j++)
            #pragma unroll
            for (int i = 0; i < 8; i++)
                Ps[(tc*4 + j)*PS_STRIDE + tr*8 + i] = s[i][j];
        __syncthreads();

        // ---- GEMM2: O += P V ----
        #pragma unroll 4
        for (int kk = 0; kk < 64; kk++) {
            float rm[8];
            #pragma unroll
            for (int i = 0; i < 8; i++) rm[i] = Ps[kk*PS_STRIDE + tr*8 + i];
            float4 rn = *reinterpret_cast<const float4*>(&Vs[kk*64 + tc*4]);
            #pragma unroll
            for (int i = 0; i < 8; i++) {
                oacc[i][0] = fmaf(rm[i], rn.x, oacc[i][0]);
                oacc[i][1] = fmaf(rm[i], rn.y, oacc[i][1]);
                oacc[i][2] = fmaf(rm[i], rn.z, oacc[i][2]);
                oacc[i][3] = fmaf(rm[i], rn.w, oacc[i][3]);
            }
        }
        __syncthreads();
    }

    // ---- finalize: divide by l and store ----
    #pragma unroll
    for (int i = 0; i < 8; i++) {
        float inv = 1.0f / l_run[i];
        float4 v = make_float4(oacc[i][0]*inv, oacc[i][1]*inv,
                               oacc[i][2]*inv, oacc[i][3]*inv);
        float* orow = ob + (size_t)(b*SEQ + q0 + tr*8 + i) * QDIM + h * HD + tc*4;
        *reinterpret_cast<float4*>(orow) = v;
    }
}

// ---------------------------------------------------------------------------
// launch
// ---------------------------------------------------------------------------
extern "C" void kernel_launch(void* const* d_in, const int* in_sizes, int n_in,
                              void* d_out, int out_size)
{
    const float* x        = (const float*)d_in[0];
    const float* rope_cos = (const float*)d_in[1];
    const float* rope_sin = (const float*)d_in[2];
    const int*   doc_ids  = (const int*)  d_in[3];
    const float* Wq       = (const float*)d_in[4];
    const float* Wk       = (const float*)d_in[5];
    const float* Wv       = (const float*)d_in[6];
    const float* Wo       = (const float*)d_in[7];
    float* out = (float*)d_out;

    float* q = nullptr; float* k = nullptr; float* v = nullptr; float* o = nullptr;
    cudaGetSymbolAddress((void**)&q, g_q);
    cudaGetSymbolAddress((void**)&k, g_k);
    cudaGetSymbolAddress((void**)&v, g_v);
    cudaGetSymbolAddress((void**)&o, g_o);

    // QKV projections
    {
        dim3 gq(QDIM/128,  MTOT/128);
        dim3 gk(KVDIM/128, MTOT/128);
        sgemm_tn<<<gq, 256>>>(x, Wq, q, MTOT, QDIM,  DIMK);
        sgemm_tn<<<gk, 256>>>(x, Wk, k, MTOT, KVDIM, DIMK);
        sgemm_tn<<<gk, 256>>>(x, Wv, v, MTOT, KVDIM, DIMK);
    }

    // RoPE (scale 1/sqrt(HD) folded into Q)
    {
        int tq = MTOT * NH  * (HD/2);
        int tk = MTOT * NKV * (HD/2);
        rope_kernel<<<(tq + 255)/256, 256>>>(q, rope_cos, rope_sin, NH,  0.125f);
        rope_kernel<<<(tk + 255)/256, 256>>>(k, rope_cos, rope_sin, NKV, 1.0f);
    }

    // doc starts
    docstart_kernel<<<(MTOT + 255)/256, 256>>>(doc_ids);

    // flash attention
    {
        static int smem_set = -1;
        int smem_bytes = FA_SMEM_FLOATS * (int)sizeof(float);
        cudaFuncSetAttribute(flash_kernel,
                             cudaFuncAttributeMaxDynamicSharedMemorySize, smem_bytes);
        (void)smem_set;
        dim3 grid(SEQ/64, NH, BATCH);
        flash_kernel<<<grid, 128, smem_bytes>>>(q, k, v, o);
    }

    // output projection
    {
        dim3 go(DIMK/128, MTOT/128);
        sgemm_tn<<<go, 256>>>(o, Wo, out, MTOT, DIMK, QDIM);
    }
}

// round 7
// speedup vs baseline: 2.0262x; 2.0262x over previous
#include <cuda_runtime.h>
#include <cuda_bf16.h>
#include <math.h>
#include <stdint.h>

// Problem constants
#define BATCH 2
#define SEQ   2048
#define DIMK  2048
#define NH    32
#define NKV   8
#define HD    64
#define NREP  4
#define MTOT  (BATCH*SEQ)      // 4096
#define QDIM  (NH*HD)          // 2048
#define KVDIM (NKV*HD)         // 512
#define K3    (3*DIMK)         // 6144 augmented K

// fp32 scratch
__device__ float g_q[MTOT*QDIM];
__device__ float g_k[MTOT*KVDIM];
__device__ float g_v[MTOT*KVDIM];
__device__ float g_o[MTOT*QDIM];
__device__ int   g_docstart[MTOT];

// bf16 split-3 scratch (K' = 6144)
__device__ __nv_bfloat16 g_xs [MTOT*K3];
__device__ __nv_bfloat16 g_wqs[QDIM*K3];
__device__ __nv_bfloat16 g_wks[KVDIM*K3];
__device__ __nv_bfloat16 g_wvs[KVDIM*K3];
__device__ __nv_bfloat16 g_wos[DIMK*K3];
__device__ __nv_bfloat16 g_os [MTOT*K3];

// ---------------------------------------------------------------------------
// split3: dst[r] = [hi | seg1 | seg2] with lo placed in segment lo_seg (1 or 2),
// the other segment gets hi. A-side uses lo_seg=1, B-side lo_seg=2 so that a
// plain dot over K'=3K computes Ah*Bh + Al*Bh + Ah*Bl.
// ---------------------------------------------------------------------------
__global__ void split3_kernel(const float* __restrict__ src,
                              __nv_bfloat16* __restrict__ dst,
                              int rows, int cols, int lo_seg)
{
    int total = rows * cols;
    for (int idx = blockIdx.x * blockDim.x + threadIdx.x; idx < total;
         idx += gridDim.x * blockDim.x) {
        int r = idx / cols, c = idx % cols;
        float v = src[idx];
        __nv_bfloat16 hi = __float2bfloat16(v);
        __nv_bfloat16 lo = __float2bfloat16(v - __bfloat162float(hi));
        size_t base = (size_t)r * (3*cols);
        dst[base + c]          = hi;
        dst[base + cols + c]   = (lo_seg == 1) ? lo : hi;
        dst[base + 2*cols + c] = (lo_seg == 2) ? lo : hi;
    }
}

// ---------------------------------------------------------------------------
// bf16 tensor-core GEMM: C[m,n] = sum_k A[m*K+k]*B[n*K+k]  (C = A@B^T)
// 128x128 block tile, BK=32, 8 warps (2m x 4n), warp tile 64x32,
// mma.sync.m16n8k16 bf16->f32, cp.async 2-stage pipeline.
// ---------------------------------------------------------------------------
#define GBK 32
#define GSTRIDE 40   // bf16 elems per smem row (80B; 5x16B -> conflict-free ldmatrix)

__device__ __forceinline__ void ldsm_x4(uint32_t& r0, uint32_t& r1,
                                        uint32_t& r2, uint32_t& r3, uint32_t addr)
{
    asm volatile("ldmatrix.sync.aligned.m8n8.x4.shared.b16 {%0,%1,%2,%3}, [%4];"
                 : "=r"(r0), "=r"(r1), "=r"(r2), "=r"(r3) : "r"(addr));
}
// NON-trans x2: B tile stored n-major/k-contiguous is already the native
// orientation for the mma.row.col B fragment.
__device__ __forceinline__ void ldsm_x2(uint32_t& r0, uint32_t& r1, uint32_t addr)
{
    asm volatile("ldmatrix.sync.aligned.m8n8.x2.shared.b16 {%0,%1}, [%2];"
                 : "=r"(r0), "=r"(r1) : "r"(addr));
}
__device__ __forceinline__ void mma16816(float* c, const uint32_t* a, const uint32_t* b)
{
    asm volatile(
        "mma.sync.aligned.m16n8k16.row.col.f32.bf16.bf16.f32 "
        "{%0,%1,%2,%3}, {%4,%5,%6,%7}, {%8,%9}, {%0,%1,%2,%3};"
        : "+f"(c[0]), "+f"(c[1]), "+f"(c[2]), "+f"(c[3])
        : "r"(a[0]), "r"(a[1]), "r"(a[2]), "r"(a[3]), "r"(b[0]), "r"(b[1]));
}
__device__ __forceinline__ void cp16(void* dst, const void* src)
{
    uint32_t d = (uint32_t)__cvta_generic_to_shared(dst);
    asm volatile("cp.async.cg.shared.global [%0], [%1], 16;" :: "r"(d), "l"(src));
}

__global__ __launch_bounds__(256) void gemm_bf16_tn(
    const __nv_bfloat16* __restrict__ A, const __nv_bfloat16* __restrict__ B,
    float* __restrict__ C, int M, int N, int K)
{
    __shared__ __nv_bfloat16 As[2][128*GSTRIDE];
    __shared__ __nv_bfloat16 Bs[2][128*GSTRIDE];

    const int tid  = threadIdx.x;
    const int m0   = blockIdx.y * 128;
    const int n0   = blockIdx.x * 128;
    const int warp = tid >> 5;
    const int lane = tid & 31;
    const int wm   = (warp >> 2) * 64;   // 0 or 64
    const int wn   = (warp & 3) * 32;    // 0,32,64,96

    // load mapping: 512 16B-chunks per tile per operand, 2 per thread
    const int lrow0 = tid >> 2;          // 0..63
    const int lcol  = (tid & 3) * 8;     // 0,8,16,24

    auto issue = [&](int kt, int stage) {
        int k0 = kt * GBK;
        #pragma unroll
        for (int i = 0; i < 2; i++) {
            int row = lrow0 + i * 64;
            cp16(&As[stage][row*GSTRIDE + lcol], A + (size_t)(m0+row)*K + k0 + lcol);
            cp16(&Bs[stage][row*GSTRIDE + lcol], B + (size_t)(n0+row)*K + k0 + lcol);
        }
        asm volatile("cp.async.commit_group;");
    };

    float acc[4][4][4];
    #pragma unroll
    for (int i = 0; i < 4; i++)
        #pragma unroll
        for (int j = 0; j < 4; j++)
            #pragma unroll
            for (int t = 0; t < 4; t++) acc[i][j][t] = 0.f;

    const int nk = K / GBK;
    issue(0, 0);

    for (int kt = 0; kt < nk; kt++) {
        int stage = kt & 1;
        if (kt + 1 < nk) {
            issue(kt + 1, stage ^ 1);
            asm volatile("cp.async.wait_group 1;");
        } else {
            asm volatile("cp.async.wait_group 0;");
        }
        __syncthreads();

        uint32_t a_base = (uint32_t)__cvta_generic_to_shared(&As[stage][0]);
        uint32_t b_base = (uint32_t)__cvta_generic_to_shared(&Bs[stage][0]);

        #pragma unroll
        for (int kk = 0; kk < GBK; kk += 16) {
            uint32_t afr[4][4], bfr[4][2];
            #pragma unroll
            for (int mi = 0; mi < 4; mi++) {
                int row = wm + mi*16 + (lane & 15);
                int col = kk + (lane >> 4) * 8;
                ldsm_x4(afr[mi][0], afr[mi][1], afr[mi][2], afr[mi][3],
                        a_base + (row*GSTRIDE + col) * 2);
            }
            #pragma unroll
            for (int ni = 0; ni < 4; ni++) {
                int row = wn + ni*8 + (lane & 7);
                int col = kk + ((lane >> 3) & 1) * 8;
                ldsm_x2(bfr[ni][0], bfr[ni][1],
                        b_base + (row*GSTRIDE + col) * 2);
            }
            #pragma unroll
            for (int mi = 0; mi < 4; mi++)
                #pragma unroll
                for (int ni = 0; ni < 4; ni++)
                    mma16816(acc[mi][ni], afr[mi], bfr[ni]);
        }
        __syncthreads();
    }

    // epilogue
    const int cr = lane >> 2;        // 0..7
    const int cc = (lane & 3) * 2;   // 0,2,4,6
    #pragma unroll
    for (int mi = 0; mi < 4; mi++) {
        #pragma unroll
        for (int ni = 0; ni < 4; ni++) {
            float* p0 = C + (size_t)(m0 + wm + mi*16 + cr) * N     + n0 + wn + ni*8 + cc;
            float* p1 = C + (size_t)(m0 + wm + mi*16 + cr + 8) * N + n0 + wn + ni*8 + cc;
            *reinterpret_cast<float2*>(p0) = make_float2(acc[mi][ni][0], acc[mi][ni][1]);
            *reinterpret_cast<float2*>(p1) = make_float2(acc[mi][ni][2], acc[mi][ni][3]);
        }
    }
}

// ---------------------------------------------------------------------------
// RoPE (in place) with folded scale.
// ---------------------------------------------------------------------------
__global__ void rope_kernel(float* __restrict__ buf,
                            const float* __restrict__ cosb,
                            const float* __restrict__ sinb,
                            int heads, float scale)
{
    int idx = blockIdx.x * blockDim.x + threadIdx.x;
    int total = MTOT * heads * (HD/2);
    if (idx >= total) return;
    int d  = idx % (HD/2);
    int h  = (idx / (HD/2)) % heads;
    int bs = idx / ((HD/2) * heads);
    int s  = bs % SEQ;
    float c  = cosb[s*(HD/2) + d];
    float sn = sinb[s*(HD/2) + d];
    float* base = buf + (size_t)bs * heads * HD + h * HD;
    float x1 = base[d];
    float x2 = base[d + HD/2];
    base[d]        = (x1*c - x2*sn) * scale;
    base[d + HD/2] = (x2*c + x1*sn) * scale;
}

// ---------------------------------------------------------------------------
// doc_start (doc_ids sorted per row)
// ---------------------------------------------------------------------------
__global__ void docstart_kernel(const int* __restrict__ doc_ids)
{
    int idx = blockIdx.x * blockDim.x + threadIdx.x;
    if (idx >= MTOT) return;
    int b = idx / SEQ, s = idx % SEQ;
    const int* row = doc_ids + b * SEQ;
    int v = row[s];
    int lo = 0, hi = s;
    while (lo < hi) {
        int mid = (lo + hi) >> 1;
        if (row[mid] < v) lo = mid + 1; else hi = mid;
    }
    g_docstart[idx] = lo;
}

// ---------------------------------------------------------------------------
// Flash attention, fp32, BQ=64 x BK=64 tiles, 128 threads.
// ---------------------------------------------------------------------------
#define QS_STRIDE 65
#define PS_STRIDE 65
#define FA_SMEM_FLOATS (64*QS_STRIDE + 64*64 + 64*64 + 64*PS_STRIDE)

__global__ __launch_bounds__(128) void flash_kernel(
    const float* __restrict__ qb, const float* __restrict__ kb,
    const float* __restrict__ vb, float* __restrict__ ob)
{
    extern __shared__ float sm[];
    float* Qs = sm;
    float* Ks = Qs + 64*QS_STRIDE;
    float* Vs = Ks + 64*64;
    float* Ps = Vs + 64*64;

    const int tid = threadIdx.x;
    const int q0  = blockIdx.x * 64;
    const int h   = blockIdx.y;
    const int b   = blockIdx.z;
    const int hk  = h / NREP;

    const int tr = tid >> 4;
    const int tc = tid & 15;

    {
        int m    = tid & 63;
        int half = tid >> 6;
        const float* qrow = qb + (size_t)(b*SEQ + q0 + m) * QDIM + h * HD;
        #pragma unroll
        for (int i = 0; i < 8; i++) {
            int d0 = half*32 + i*4;
            float4 v = *reinterpret_cast<const float4*>(qrow + d0);
            Qs[(d0+0)*QS_STRIDE + m] = v.x;
            Qs[(d0+1)*QS_STRIDE + m] = v.y;
            Qs[(d0+2)*QS_STRIDE + m] = v.z;
            Qs[(d0+3)*QS_STRIDE + m] = v.w;
        }
    }

    int   myds[8];
    float m_run[8], l_run[8], oacc[8][4];
    #pragma unroll
    for (int i = 0; i < 8; i++) {
        myds[i]  = g_docstart[b*SEQ + q0 + tr*8 + i];
        m_run[i] = -1e30f;
        l_run[i] = 0.f;
        #pragma unroll
        for (int j = 0; j < 4; j++) oacc[i][j] = 0.f;
    }

    const int kstart = g_docstart[b*SEQ + q0] & ~63;
    __syncthreads();

    for (int k0 = kstart; k0 <= q0; k0 += 64) {
        {
            int j    = tid & 63;
            int half = tid >> 6;
            const float* krow = kb + (size_t)(b*SEQ + k0 + j) * KVDIM + hk * HD;
            #pragma unroll
            for (int i = 0; i < 8; i++) {
                int d0 = half*32 + i*4;
                float4 v = *reinterpret_cast<const float4*>(krow + d0);
                Ks[(d0+0)*64 + j] = v.x;
                Ks[(d0+1)*64 + j] = v.y;
                Ks[(d0+2)*64 + j] = v.z;
                Ks[(d0+3)*64 + j] = v.w;
            }
            int jv = tid >> 4;
            int d0 = (tid & 15) * 4;
            #pragma unroll
            for (int it = 0; it < 8; it++) {
                int jj = jv + it*8;
                const float* vrow = vb + (size_t)(b*SEQ + k0 + jj) * KVDIM + hk * HD;
                float4 v = *reinterpret_cast<const float4*>(vrow + d0);
                *reinterpret_cast<float4*>(&Vs[jj*64 + d0]) = v;
            }
        }
        __syncthreads();

        float s[8][4];
        #pragma unroll
        for (int i = 0; i < 8; i++)
            #pragma unroll
            for (int j = 0; j < 4; j++) s[i][j] = 0.f;

        #pragma unroll 4
        for (int kk = 0; kk < 64; kk++) {
            float rm[8];
            #pragma unroll
            for (int i = 0; i < 8; i++) rm[i] = Qs[kk*QS_STRIDE + tr*8 + i];
            float4 rn = *reinterpret_cast<const float4*>(&Ks[kk*64 + tc*4]);
            #pragma unroll
            for (int i = 0; i < 8; i++) {
                s[i][0] = fmaf(rm[i], rn.x, s[i][0]);
                s[i][1] = fmaf(rm[i], rn.y, s[i][1]);
                s[i][2] = fmaf(rm[i], rn.z, s[i][2]);
                s[i][3] = fmaf(rm[i], rn.w, s[i][3]);
            }
        }

        #pragma unroll
        for (int i = 0; i < 8; i++) {
            int qi = q0 + tr*8 + i;
            float mloc = -1e30f;
            #pragma unroll
            for (int j = 0; j < 4; j++) {
                int kj = k0 + tc*4 + j;
                bool ok = (kj <= qi) && (kj >= myds[i]);
                if (!ok) s[i][j] = -1e30f;
                mloc = fmaxf(mloc, s[i][j]);
            }
            #pragma unroll
            for (int off = 8; off > 0; off >>= 1)
                mloc = fmaxf(mloc, __shfl_xor_sync(0xffffffffu, mloc, off));

            float mnew = fmaxf(m_run[i], mloc);
            float corr = __expf(m_run[i] - mnew);
            m_run[i] = mnew;

            float lsum = 0.f;
            #pragma unroll
            for (int j = 0; j < 4; j++) {
                float p = (s[i][j] > -1e29f) ? __expf(s[i][j] - mnew) : 0.f;
                s[i][j] = p;
                lsum += p;
            }
            #pragma unroll
            for (int off = 8; off > 0; off >>= 1)
                lsum += __shfl_xor_sync(0xffffffffu, lsum, off);

            l_run[i] = l_run[i] * corr + lsum;
            #pragma unroll
            for (int d = 0; d < 4; d++) oacc[i][d] *= corr;
        }

        #pragma unroll
        for (int j = 0; j < 4; j++)
            #pragma unroll
            for (int i = 0; i < 8; i++)
                Ps[(tc*4 + j)*PS_STRIDE + tr*8 + i] = s[i][j];
        __syncthreads();

        #pragma unroll 4
        for (int kk = 0; kk < 64; kk++) {
            float rm[8];
            #pragma unroll
            for (int i = 0; i < 8; i++) rm[i] = Ps[kk*PS_STRIDE + tr*8 + i];
            float4 rn = *reinterpret_cast<const float4*>(&Vs[kk*64 + tc*4]);
            #pragma unroll
            for (int i = 0; i < 8; i++) {
                oacc[i][0] = fmaf(rm[i], rn.x, oacc[i][0]);
                oacc[i][1] = fmaf(rm[i], rn.y, oacc[i][1]);
                oacc[i][2] = fmaf(rm[i], rn.z, oacc[i][2]);
                oacc[i][3] = fmaf(rm[i], rn.w, oacc[i][3]);
            }
        }
        __syncthreads();
    }

    #pragma unroll
    for (int i = 0; i < 8; i++) {
        float inv = 1.0f / l_run[i];
        float4 v = make_float4(oacc[i][0]*inv, oacc[i][1]*inv,
                               oacc[i][2]*inv, oacc[i][3]*inv);
        float* orow = ob + (size_t)(b*SEQ + q0 + tr*8 + i) * QDIM + h * HD + tc*4;
        *reinterpret_cast<float4*>(orow) = v;
    }
}

// ---------------------------------------------------------------------------
// launch
// ---------------------------------------------------------------------------
extern "C" void kernel_launch(void* const* d_in, const int* in_sizes, int n_in,
                              void* d_out, int out_size)
{
    const float* x        = (const float*)d_in[0];
    const float* rope_cos = (const float*)d_in[1];
    const float* rope_sin = (const float*)d_in[2];
    const int*   doc_ids  = (const int*)  d_in[3];
    const float* Wq       = (const float*)d_in[4];
    const float* Wk       = (const float*)d_in[5];
    const float* Wv       = (const float*)d_in[6];
    const float* Wo       = (const float*)d_in[7];
    float* out = (float*)d_out;

    float *q, *k, *v, *o;
    __nv_bfloat16 *xs, *wqs, *wks, *wvs, *wos, *os;
    cudaGetSymbolAddress((void**)&q,  g_q);
    cudaGetSymbolAddress((void**)&k,  g_k);
    cudaGetSymbolAddress((void**)&v,  g_v);
    cudaGetSymbolAddress((void**)&o,  g_o);
    cudaGetSymbolAddress((void**)&xs,  g_xs);
    cudaGetSymbolAddress((void**)&wqs, g_wqs);
    cudaGetSymbolAddress((void**)&wks, g_wks);
    cudaGetSymbolAddress((void**)&wvs, g_wvs);
    cudaGetSymbolAddress((void**)&wos, g_wos);
    cudaGetSymbolAddress((void**)&os,  g_os);

    const int CT = 256, CG = 1024;

    // split conversions (A-side lo_seg=1, B-side lo_seg=2)
    split3_kernel<<<CG, CT>>>(x,  xs,  MTOT,  DIMK, 1);
    split3_kernel<<<CG, CT>>>(Wq, wqs, QDIM,  DIMK, 2);
    split3_kernel<<<CG, CT>>>(Wk, wks, KVDIM, DIMK, 2);
    split3_kernel<<<CG, CT>>>(Wv, wvs, KVDIM, DIMK, 2);
    split3_kernel<<<CG, CT>>>(Wo, wos, DIMK,  QDIM, 2);

    // QKV projections on tensor cores
    {
        dim3 gq(QDIM/128,  MTOT/128);
        dim3 gk(KVDIM/128, MTOT/128);
        gemm_bf16_tn<<<gq, 256>>>(xs, wqs, q, MTOT, QDIM,  K3);
        gemm_bf16_tn<<<gk, 256>>>(xs, wks, k, MTOT, KVDIM, K3);
        gemm_bf16_tn<<<gk, 256>>>(xs, wvs, v, MTOT, KVDIM, K3);
    }

    // RoPE (1/sqrt(HD) folded into Q)
    {
        int tq = MTOT * NH  * (HD/2);
        int tk = MTOT * NKV * (HD/2);
        rope_kernel<<<(tq + 255)/256, 256>>>(q, rope_cos, rope_sin, NH,  0.125f);
        rope_kernel<<<(tk + 255)/256, 256>>>(k, rope_cos, rope_sin, NKV, 1.0f);
    }

    docstart_kernel<<<(MTOT + 255)/256, 256>>>(doc_ids);

    // flash attention
    {
        int smem_bytes = FA_SMEM_FLOATS * (int)sizeof(float);
        cudaFuncSetAttribute(flash_kernel,
                             cudaFuncAttributeMaxDynamicSharedMemorySize, smem_bytes);
        dim3 grid(SEQ/64, NH, BATCH);
        flash_kernel<<<grid, 128, smem_bytes>>>(q, k, v, o);
    }

    // output projection: split o, then tensor-core GEMM
    split3_kernel<<<CG, CT>>>(o, os, MTOT, QDIM, 1);
    {
        dim3 go(DIMK/128, MTOT/128);
        gemm_bf16_tn<<<go, 256>>>(os, wos, out, MTOT, DIMK, K3);
    }
}

// round 8
// speedup vs baseline: 2.0270x; 1.0004x over previous
#include <cuda_runtime.h>
#include <cuda_bf16.h>
#include <math.h>
#include <stdint.h>

// Problem constants
#define BATCH 2
#define SEQ   2048
#define DIMK  2048
#define NH    32
#define NKV   8
#define HD    64
#define NREP  4
#define MTOT  (BATCH*SEQ)      // 4096
#define QDIM  (NH*HD)          // 2048
#define KVDIM (NKV*HD)         // 512
#define K3    (3*DIMK)         // 6144 augmented K

// fp32 scratch
__device__ float g_q[MTOT*QDIM];
__device__ float g_k[MTOT*KVDIM];
__device__ float g_v[MTOT*KVDIM];
__device__ float g_o[MTOT*QDIM];
__device__ int   g_docstart[MTOT];

// bf16 split-3 scratch (K' = 6144)
__device__ __nv_bfloat16 g_xs [MTOT*K3];
__device__ __nv_bfloat16 g_wqs[QDIM*K3];
__device__ __nv_bfloat16 g_wks[KVDIM*K3];
__device__ __nv_bfloat16 g_wvs[KVDIM*K3];
__device__ __nv_bfloat16 g_wos[DIMK*K3];
__device__ __nv_bfloat16 g_os [MTOT*K3];

// ---------------------------------------------------------------------------
// split3: dst[r] = [hi | seg1 | seg2] with lo placed in segment lo_seg (1 or 2),
// the other segment gets hi. A-side uses lo_seg=1, B-side lo_seg=2 so that a
// plain dot over K'=3K computes Ah*Bh + Al*Bh + Ah*Bl.
// ---------------------------------------------------------------------------
__global__ void split3_kernel(const float* __restrict__ src,
                              __nv_bfloat16* __restrict__ dst,
                              int rows, int cols, int lo_seg)
{
    int total = rows * cols;
    for (int idx = blockIdx.x * blockDim.x + threadIdx.x; idx < total;
         idx += gridDim.x * blockDim.x) {
        int r = idx / cols, c = idx % cols;
        float v = src[idx];
        __nv_bfloat16 hi = __float2bfloat16(v);
        __nv_bfloat16 lo = __float2bfloat16(v - __bfloat162float(hi));
        size_t base = (size_t)r * (3*cols);
        dst[base + c]          = hi;
        dst[base + cols + c]   = (lo_seg == 1) ? lo : hi;
        dst[base + 2*cols + c] = (lo_seg == 2) ? lo : hi;
    }
}

// ---------------------------------------------------------------------------
// bf16 tensor-core GEMM: C[m,n] = sum_k A[m*K+k]*B[n*K+k]  (C = A@B^T)
// 128x128 block tile, BK=32, 8 warps (2m x 4n), warp tile 64x32,
// mma.sync.m16n8k16 bf16->f32, cp.async 2-stage pipeline.
// ---------------------------------------------------------------------------
#define GBK 32
#define GSTRIDE 40   // bf16 elems per smem row (80B; 5x16B -> conflict-free ldmatrix)

__device__ __forceinline__ void ldsm_x4(uint32_t& r0, uint32_t& r1,
                                        uint32_t& r2, uint32_t& r3, uint32_t addr)
{
    asm volatile("ldmatrix.sync.aligned.m8n8.x4.shared.b16 {%0,%1,%2,%3}, [%4];"
                 : "=r"(r0), "=r"(r1), "=r"(r2), "=r"(r3) : "r"(addr));
}
// NON-trans x2: B tile stored n-major/k-contiguous is already the native
// orientation for the mma.row.col B fragment.
__device__ __forceinline__ void ldsm_x2(uint32_t& r0, uint32_t& r1, uint32_t addr)
{
    asm volatile("ldmatrix.sync.aligned.m8n8.x2.shared.b16 {%0,%1}, [%2];"
                 : "=r"(r0), "=r"(r1) : "r"(addr));
}
__device__ __forceinline__ void mma16816(float* c, const uint32_t* a, const uint32_t* b)
{
    asm volatile(
        "mma.sync.aligned.m16n8k16.row.col.f32.bf16.bf16.f32 "
        "{%0,%1,%2,%3}, {%4,%5,%6,%7}, {%8,%9}, {%0,%1,%2,%3};"
        : "+f"(c[0]), "+f"(c[1]), "+f"(c[2]), "+f"(c[3])
        : "r"(a[0]), "r"(a[1]), "r"(a[2]), "r"(a[3]), "r"(b[0]), "r"(b[1]));
}
__device__ __forceinline__ void cp16(void* dst, const void* src)
{
    uint32_t d = (uint32_t)__cvta_generic_to_shared(dst);
    asm volatile("cp.async.cg.shared.global [%0], [%1], 16;" :: "r"(d), "l"(src));
}

__global__ __launch_bounds__(256) void gemm_bf16_tn(
    const __nv_bfloat16* __restrict__ A, const __nv_bfloat16* __restrict__ B,
    float* __restrict__ C, int M, int N, int K)
{
    __shared__ __nv_bfloat16 As[2][128*GSTRIDE];
    __shared__ __nv_bfloat16 Bs[2][128*GSTRIDE];

    const int tid  = threadIdx.x;
    const int m0   = blockIdx.y * 128;
    const int n0   = blockIdx.x * 128;
    const int warp = tid >> 5;
    const int lane = tid & 31;
    const int wm   = (warp >> 2) * 64;   // 0 or 64
    const int wn   = (warp & 3) * 32;    // 0,32,64,96

    // load mapping: 512 16B-chunks per tile per operand, 2 per thread
    const int lrow0 = tid >> 2;          // 0..63
    const int lcol  = (tid & 3) * 8;     // 0,8,16,24

    auto issue = [&](int kt, int stage) {
        int k0 = kt * GBK;
        #pragma unroll
        for (int i = 0; i < 2; i++) {
            int row = lrow0 + i * 64;
            cp16(&As[stage][row*GSTRIDE + lcol], A + (size_t)(m0+row)*K + k0 + lcol);
            cp16(&Bs[stage][row*GSTRIDE + lcol], B + (size_t)(n0+row)*K + k0 + lcol);
        }
        asm volatile("cp.async.commit_group;");
    };

    float acc[4][4][4];
    #pragma unroll
    for (int i = 0; i < 4; i++)
        #pragma unroll
        for (int j = 0; j < 4; j++)
            #pragma unroll
            for (int t = 0; t < 4; t++) acc[i][j][t] = 0.f;

    const int nk = K / GBK;
    issue(0, 0);

    for (int kt = 0; kt < nk; kt++) {
        int stage = kt & 1;
        if (kt + 1 < nk) {
            issue(kt + 1, stage ^ 1);
            asm volatile("cp.async.wait_group 1;");
        } else {
            asm volatile("cp.async.wait_group 0;");
        }
        __syncthreads();

        uint32_t a_base = (uint32_t)__cvta_generic_to_shared(&As[stage][0]);
        uint32_t b_base = (uint32_t)__cvta_generic_to_shared(&Bs[stage][0]);

        #pragma unroll
        for (int kk = 0; kk < GBK; kk += 16) {
            uint32_t afr[4][4], bfr[4][2];
            #pragma unroll
            for (int mi = 0; mi < 4; mi++) {
                int row = wm + mi*16 + (lane & 15);
                int col = kk + (lane >> 4) * 8;
                ldsm_x4(afr[mi][0], afr[mi][1], afr[mi][2], afr[mi][3],
                        a_base + (row*GSTRIDE + col) * 2);
            }
            #pragma unroll
            for (int ni = 0; ni < 4; ni++) {
                int row = wn + ni*8 + (lane & 7);
                int col = kk + ((lane >> 3) & 1) * 8;
                ldsm_x2(bfr[ni][0], bfr[ni][1],
                        b_base + (row*GSTRIDE + col) * 2);
            }
            #pragma unroll
            for (int mi = 0; mi < 4; mi++)
                #pragma unroll
                for (int ni = 0; ni < 4; ni++)
                    mma16816(acc[mi][ni], afr[mi], bfr[ni]);
        }
        __syncthreads();
    }

    // epilogue
    const int cr = lane >> 2;        // 0..7
    const int cc = (lane & 3) * 2;   // 0,2,4,6
    #pragma unroll
    for (int mi = 0; mi < 4; mi++) {
        #pragma unroll
        for (int ni = 0; ni < 4; ni++) {
            float* p0 = C + (size_t)(m0 + wm + mi*16 + cr) * N     + n0 + wn + ni*8 + cc;
            float* p1 = C + (size_t)(m0 + wm + mi*16 + cr + 8) * N + n0 + wn + ni*8 + cc;
            *reinterpret_cast<float2*>(p0) = make_float2(acc[mi][ni][0], acc[mi][ni][1]);
            *reinterpret_cast<float2*>(p1) = make_float2(acc[mi][ni][2], acc[mi][ni][3]);
        }
    }
}

// ---------------------------------------------------------------------------
// RoPE (in place) with folded scale.
// ---------------------------------------------------------------------------
__global__ void rope_kernel(float* __restrict__ buf,
                            const float* __restrict__ cosb,
                            const float* __restrict__ sinb,
                            int heads, float scale)
{
    int idx = blockIdx.x * blockDim.x + threadIdx.x;
    int total = MTOT * heads * (HD/2);
    if (idx >= total) return;
    int d  = idx % (HD/2);
    int h  = (idx / (HD/2)) % heads;
    int bs = idx / ((HD/2) * heads);
    int s  = bs % SEQ;
    float c  = cosb[s*(HD/2) + d];
    float sn = sinb[s*(HD/2) + d];
    float* base = buf + (size_t)bs * heads * HD + h * HD;
    float x1 = base[d];
    float x2 = base[d + HD/2];
    base[d]        = (x1*c - x2*sn) * scale;
    base[d + HD/2] = (x2*c + x1*sn) * scale;
}

// ---------------------------------------------------------------------------
// doc_start (doc_ids sorted per row)
// ---------------------------------------------------------------------------
__global__ void docstart_kernel(const int* __restrict__ doc_ids)
{
    int idx = blockIdx.x * blockDim.x + threadIdx.x;
    if (idx >= MTOT) return;
    int b = idx / SEQ, s = idx % SEQ;
    const int* row = doc_ids + b * SEQ;
    int v = row[s];
    int lo = 0, hi = s;
    while (lo < hi) {
        int mid = (lo + hi) >> 1;
        if (row[mid] < v) lo = mid + 1; else hi = mid;
    }
    g_docstart[idx] = lo;
}

// ---------------------------------------------------------------------------
// Flash attention, fp32, BQ=64 x BK=64 tiles, 128 threads.
// ---------------------------------------------------------------------------
#define QS_STRIDE 65
#define PS_STRIDE 65
#define FA_SMEM_FLOATS (64*QS_STRIDE + 64*64 + 64*64 + 64*PS_STRIDE)

__global__ __launch_bounds__(128) void flash_kernel(
    const float* __restrict__ qb, const float* __restrict__ kb,
    const float* __restrict__ vb, float* __restrict__ ob)
{
    extern __shared__ float sm[];
    float* Qs = sm;
    float* Ks = Qs + 64*QS_STRIDE;
    float* Vs = Ks + 64*64;
    float* Ps = Vs + 64*64;

    const int tid = threadIdx.x;
    const int q0  = blockIdx.x * 64;
    const int h   = blockIdx.y;
    const int b   = blockIdx.z;
    const int hk  = h / NREP;

    const int tr = tid >> 4;
    const int tc = tid & 15;

    {
        int m    = tid & 63;
        int half = tid >> 6;
        const float* qrow = qb + (size_t)(b*SEQ + q0 + m) * QDIM + h * HD;
        #pragma unroll
        for (int i = 0; i < 8; i++) {
            int d0 = half*32 + i*4;
            float4 v = *reinterpret_cast<const float4*>(qrow + d0);
            Qs[(d0+0)*QS_STRIDE + m] = v.x;
            Qs[(d0+1)*QS_STRIDE + m] = v.y;
            Qs[(d0+2)*QS_STRIDE + m] = v.z;
            Qs[(d0+3)*QS_STRIDE + m] = v.w;
        }
    }

    int   myds[8];
    float m_run[8], l_run[8], oacc[8][4];
    #pragma unroll
    for (int i = 0; i < 8; i++) {
        myds[i]  = g_docstart[b*SEQ + q0 + tr*8 + i];
        m_run[i] = -1e30f;
        l_run[i] = 0.f;
        #pragma unroll
        for (int j = 0; j < 4; j++) oacc[i][j] = 0.f;
    }

    const int kstart = g_docstart[b*SEQ + q0] & ~63;
    __syncthreads();

    for (int k0 = kstart; k0 <= q0; k0 += 64) {
        {
            int j    = tid & 63;
            int half = tid >> 6;
            const float* krow = kb + (size_t)(b*SEQ + k0 + j) * KVDIM + hk * HD;
            #pragma unroll
            for (int i = 0; i < 8; i++) {
                int d0 = half*32 + i*4;
                float4 v = *reinterpret_cast<const float4*>(krow + d0);
                Ks[(d0+0)*64 + j] = v.x;
                Ks[(d0+1)*64 + j] = v.y;
                Ks[(d0+2)*64 + j] = v.z;
                Ks[(d0+3)*64 + j] = v.w;
            }
            int jv = tid >> 4;
            int d0 = (tid & 15) * 4;
            #pragma unroll
            for (int it = 0; it < 8; it++) {
                int jj = jv + it*8;
                const float* vrow = vb + (size_t)(b*SEQ + k0 + jj) * KVDIM + hk * HD;
                float4 v = *reinterpret_cast<const float4*>(vrow + d0);
                *reinterpret_cast<float4*>(&Vs[jj*64 + d0]) = v;
            }
        }
        __syncthreads();

        float s[8][4];
        #pragma unroll
        for (int i = 0; i < 8; i++)
            #pragma unroll
            for (int j = 0; j < 4; j++) s[i][j] = 0.f;

        #pragma unroll 4
        for (int kk = 0; kk < 64; kk++) {
            float rm[8];
            #pragma unroll
            for (int i = 0; i < 8; i++) rm[i] = Qs[kk*QS_STRIDE + tr*8 + i];
            float4 rn = *reinterpret_cast<const float4*>(&Ks[kk*64 + tc*4]);
            #pragma unroll
            for (int i = 0; i < 8; i++) {
                s[i][0] = fmaf(rm[i], rn.x, s[i][0]);
                s[i][1] = fmaf(rm[i], rn.y, s[i][1]);
                s[i][2] = fmaf(rm[i], rn.z, s[i][2]);
                s[i][3] = fmaf(rm[i], rn.w, s[i][3]);
            }
        }

        #pragma unroll
        for (int i = 0; i < 8; i++) {
            int qi = q0 + tr*8 + i;
            float mloc = -1e30f;
            #pragma unroll
            for (int j = 0; j < 4; j++) {
                int kj = k0 + tc*4 + j;
                bool ok = (kj <= qi) && (kj >= myds[i]);
                if (!ok) s[i][j] = -1e30f;
                mloc = fmaxf(mloc, s[i][j]);
            }
            #pragma unroll
            for (int off = 8; off > 0; off >>= 1)
                mloc = fmaxf(mloc, __shfl_xor_sync(0xffffffffu, mloc, off));

            float mnew = fmaxf(m_run[i], mloc);
            float corr = __expf(m_run[i] - mnew);
            m_run[i] = mnew;

            float lsum = 0.f;
            #pragma unroll
            for (int j = 0; j < 4; j++) {
                float p = (s[i][j] > -1e29f) ? __expf(s[i][j] - mnew) : 0.f;
                s[i][j] = p;
                lsum += p;
            }
            #pragma unroll
            for (int off = 8; off > 0; off >>= 1)
                lsum += __shfl_xor_sync(0xffffffffu, lsum, off);

            l_run[i] = l_run[i] * corr + lsum;
            #pragma unroll
            for (int d = 0; d < 4; d++) oacc[i][d] *= corr;
        }

        #pragma unroll
        for (int j = 0; j < 4; j++)
            #pragma unroll
            for (int i = 0; i < 8; i++)
                Ps[(tc*4 + j)*PS_STRIDE + tr*8 + i] = s[i][j];
        __syncthreads();

        #pragma unroll 4
        for (int kk = 0; kk < 64; kk++) {
            float rm[8];
            #pragma unroll
            for (int i = 0; i < 8; i++) rm[i] = Ps[kk*PS_STRIDE + tr*8 + i];
            float4 rn = *reinterpret_cast<const float4*>(&Vs[kk*64 + tc*4]);
            #pragma unroll
            for (int i = 0; i < 8; i++) {
                oacc[i][0] = fmaf(rm[i], rn.x, oacc[i][0]);
                oacc[i][1] = fmaf(rm[i], rn.y, oacc[i][1]);
                oacc[i][2] = fmaf(rm[i], rn.z, oacc[i][2]);
                oacc[i][3] = fmaf(rm[i], rn.w, oacc[i][3]);
            }
        }
        __syncthreads();
    }

    #pragma unroll
    for (int i = 0; i < 8; i++) {
        float inv = 1.0f / l_run[i];
        float4 v = make_float4(oacc[i][0]*inv, oacc[i][1]*inv,
                               oacc[i][2]*inv, oacc[i][3]*inv);
        float* orow = ob + (size_t)(b*SEQ + q0 + tr*8 + i) * QDIM + h * HD + tc*4;
        *reinterpret_cast<float4*>(orow) = v;
    }
}

// ---------------------------------------------------------------------------
// launch
// ---------------------------------------------------------------------------
extern "C" void kernel_launch(void* const* d_in, const int* in_sizes, int n_in,
                              void* d_out, int out_size)
{
    const float* x        = (const float*)d_in[0];
    const float* rope_cos = (const float*)d_in[1];
    const float* rope_sin = (const float*)d_in[2];
    const int*   doc_ids  = (const int*)  d_in[3];
    const float* Wq       = (const float*)d_in[4];
    const float* Wk       = (const float*)d_in[5];
    const float* Wv       = (const float*)d_in[6];
    const float* Wo       = (const float*)d_in[7];
    float* out = (float*)d_out;

    float *q, *k, *v, *o;
    __nv_bfloat16 *xs, *wqs, *wks, *wvs, *wos, *os;
    cudaGetSymbolAddress((void**)&q,  g_q);
    cudaGetSymbolAddress((void**)&k,  g_k);
    cudaGetSymbolAddress((void**)&v,  g_v);
    cudaGetSymbolAddress((void**)&o,  g_o);
    cudaGetSymbolAddress((void**)&xs,  g_xs);
    cudaGetSymbolAddress((void**)&wqs, g_wqs);
    cudaGetSymbolAddress((void**)&wks, g_wks);
    cudaGetSymbolAddress((void**)&wvs, g_wvs);
    cudaGetSymbolAddress((void**)&wos, g_wos);
    cudaGetSymbolAddress((void**)&os,  g_os);

    const int CT = 256, CG = 1024;

    // split conversions (A-side lo_seg=1, B-side lo_seg=2)
    split3_kernel<<<CG, CT>>>(x,  xs,  MTOT,  DIMK, 1);
    split3_kernel<<<CG, CT>>>(Wq, wqs, QDIM,  DIMK, 2);
    split3_kernel<<<CG, CT>>>(Wk, wks, KVDIM, DIMK, 2);
    split3_kernel<<<CG, CT>>>(Wv, wvs, KVDIM, DIMK, 2);
    split3_kernel<<<CG, CT>>>(Wo, wos, DIMK,  QDIM, 2);

    // QKV projections on tensor cores
    {
        dim3 gq(QDIM/128,  MTOT/128);
        dim3 gk(KVDIM/128, MTOT/128);
        gemm_bf16_tn<<<gq, 256>>>(xs, wqs, q, MTOT, QDIM,  K3);
        gemm_bf16_tn<<<gk, 256>>>(xs, wks, k, MTOT, KVDIM, K3);
        gemm_bf16_tn<<<gk, 256>>>(xs, wvs, v, MTOT, KVDIM, K3);
    }

    // RoPE (1/sqrt(HD) folded into Q)
    {
        int tq = MTOT * NH  * (HD/2);
        int tk = MTOT * NKV * (HD/2);
        rope_kernel<<<(tq + 255)/256, 256>>>(q, rope_cos, rope_sin, NH,  0.125f);
        rope_kernel<<<(tk + 255)/256, 256>>>(k, rope_cos, rope_sin, NKV, 1.0f);
    }

    docstart_kernel<<<(MTOT + 255)/256, 256>>>(doc_ids);

    // flash attention
    {
        int smem_bytes = FA_SMEM_FLOATS * (int)sizeof(float);
        cudaFuncSetAttribute(flash_kernel,
                             cudaFuncAttributeMaxDynamicSharedMemorySize, smem_bytes);
        dim3 grid(SEQ/64, NH, BATCH);
        flash_kernel<<<grid, 128, smem_bytes>>>(q, k, v, o);
    }

    // output projection: split o, then tensor-core GEMM
    split3_kernel<<<CG, CT>>>(o, os, MTOT, QDIM, 1);
    {
        dim3 go(DIMK/128, MTOT/128);
        gemm_bf16_tn<<<go, 256>>>(os, wos, out, MTOT, DIMK, K3);
    }
}